// round 9
// baseline (speedup 1.0000x reference)
#include <cuda_runtime.h>

// Problem constants (fixed by the reference setup)
#define B_ROWS 32
#define NHITS  200
#define TOT_HITS (B_ROWS * NHITS)   // 6400
#define D0     6144
#define D1     350
#define OUT_N  5
#define NTHREADS 256
#define FULL_MASK 0xFFFFFFFFu

// Single kernel. Block r OWNS output row r:
//   out[r, :] = bias + sum over UNIQUE (i0,i1) among all hits with bv == r
//               of W[i0*D1 + i1, :]
// Matches tensor_scatter_nd_update(.set(1.0)) semantics exactly (duplicates
// counted once, even across different x-rows). No global atomics, no separate
// bias-init kernel: every out element is written unconditionally by exactly
// one block (d_out poisoning is fully overwritten).
__global__ void __launch_bounds__(NTHREADS, 1)
scatter_gemv_kernel(const int* __restrict__ x,
                    const float* __restrict__ W,
                    const float* __restrict__ bias,
                    float* __restrict__ out) {
    __shared__ int   sf[TOT_HITS];   // feature indices of hits matching this row
    __shared__ int   scount;
    __shared__ float sacc[OUT_N];

    const int t    = threadIdx.x;
    const int lane = t & 31;
    const int r    = blockIdx.x;

    if (t == 0) scount = 0;
    if (t < OUT_N) sacc[t] = 0.0f;
    __syncthreads();

    // ---- Phase 1: scan all hits, compact those with bv == r into sf[] ----
    // TOT_HITS / NTHREADS = 25 exact iterations -> all threads always active,
    // full-mask warp intrinsics are safe. x is L2-resident after block 0's
    // pass (76.8 KB total), so per-block cost is mostly issue-bound.
    #pragma unroll 5
    for (int i = t; i < TOT_HITS; i += NTHREADS) {
        const int* h = x + i * 3;
        int bv = h[0];
        int f  = h[1] * D1 + h[2];
        bool match = (bv == r);
        unsigned bal = __ballot_sync(FULL_MASK, match);
        if (bal) {
            int base = 0;
            if (lane == 0) base = atomicAdd(&scount, __popc(bal));
            base = __shfl_sync(FULL_MASK, base, 0);
            if (match) {
                int pos = base + __popc(bal & ((1u << lane) - 1u));
                sf[pos] = f;
            }
        }
    }
    __syncthreads();

    const int m = scount;   // ~200 for the reference data; <= 6400 always

    // ---- Phase 2: gather (issued FIRST) overlapped with dedup ----
    // The W-row loads depend only on sf[j], not on the keep decision, so we
    // issue them before the O(m) dedup loop: their DRAM latency (~600 cyc)
    // overlaps the ~2*m cycles of broadcast-LDS dedup compute instead of
    // serializing after it. Gathering a soon-dropped duplicate row is
    // harmless (rare + L2-hit).
    float c0 = 0.f, c1 = 0.f, c2 = 0.f, c3 = 0.f, c4 = 0.f;
    for (int j = t; j < m; j += NTHREADS) {
        int key = sf[j];
        const float* w = W + (long long)key * OUT_N;
        float w0 = __ldg(w + 0);
        float w1 = __ldg(w + 1);
        float w2 = __ldg(w + 2);
        float w3 = __ldg(w + 3);
        float w4 = __ldg(w + 4);

        // Entry j survives iff no earlier entry k<j has the same feature.
        // (sf[] order is nondeterministic, but "one representative per unique
        //  value" is order-agnostic for the final sum.)
        bool keep = true;
        #pragma unroll 8
        for (int k = 0; k < m; k++) {        // broadcast LDS, conflict-free
            int kk = sf[k];
            if (k < j && kk == key) keep = false;
        }
        if (keep) {
            c0 += w0; c1 += w1; c2 += w2; c3 += w3; c4 += w4;
        }
    }

    // ---- Phase 3: reduce (warp butterfly, then 8 tiny shared atomics) ----
    #pragma unroll
    for (int off = 16; off > 0; off >>= 1) {
        c0 += __shfl_xor_sync(FULL_MASK, c0, off);
        c1 += __shfl_xor_sync(FULL_MASK, c1, off);
        c2 += __shfl_xor_sync(FULL_MASK, c2, off);
        c3 += __shfl_xor_sync(FULL_MASK, c3, off);
        c4 += __shfl_xor_sync(FULL_MASK, c4, off);
    }
    if (lane == 0) {
        atomicAdd(&sacc[0], c0);
        atomicAdd(&sacc[1], c1);
        atomicAdd(&sacc[2], c2);
        atomicAdd(&sacc[3], c3);
        atomicAdd(&sacc[4], c4);
    }
    __syncthreads();

    // ---- Phase 4: plain store (no init kernel needed) ----
    if (t < OUT_N) {
        out[r * OUT_N + t] = bias[t] + sacc[t];
    }
}

extern "C" void kernel_launch(void* const* d_in, const int* in_sizes, int n_in,
                              void* d_out, int out_size) {
    // Identify inputs by element count (robust to metadata ordering):
    //   x    : 32*200*3 = 19200 int32
    //   W    : 2150400*5 = 10752000 float32 (largest)
    //   bias : 5 float32
    const int*   x    = nullptr;
    const float* W    = nullptr;
    const float* bias = nullptr;
    long long wmax = -1;
    for (int i = 0; i < n_in; i++) {
        long long sz = in_sizes[i];
        if (sz == TOT_HITS * 3) {
            x = (const int*)d_in[i];
        } else if (sz == OUT_N) {
            bias = (const float*)d_in[i];
        } else if (sz > wmax) {
            wmax = sz;
            W = (const float*)d_in[i];
        }
    }

    scatter_gemv_kernel<<<B_ROWS, NTHREADS>>>(x, W, bias, (float*)d_out);
}